// round 7
// baseline (speedup 1.0000x reference)
#include <cuda_runtime.h>

#define Bn   16
#define CIN  64
#define COUT 64
#define Hn   130
#define Wn   130
#define HOn  128
#define WOn  128
#define Gn   8
#define CPGn 8
#define OFFC 144   // G*2*K*K
#define HWo  16384 // 128*128
#define HWi  16900 // 130*130

// Intermediate feature map t = conv3x3(x, w1) + b1  : [16,64,128,128]
__device__ float g_t[(size_t)Bn * CIN * HOn * WOn];

// ---- packed fp32x2 helpers (Blackwell FFMA2, PTX-only) ---------------------
__device__ __forceinline__ unsigned long long pack2(float v) {
    unsigned long long r;
    asm("mov.b64 %0, {%1, %1};" : "=l"(r) : "f"(v));
    return r;
}
__device__ __forceinline__ void ffma2(unsigned long long& a,
                                      unsigned long long w,
                                      unsigned long long v) {
    asm("fma.rn.f32x2 %0, %1, %2, %0;" : "+l"(a) : "l"(w), "l"(v));
}
__device__ __forceinline__ void unpack2(unsigned long long a, float& lo, float& hi) {
    asm("mov.b64 {%0, %1}, %2;" : "=f"(lo), "=f"(hi) : "l"(a));
}

// ---------------------------------------------------------------------------
// Kernel 1: 3x3 VALID conv, 64->64.
// Tile 32x16 spatial x 32 out-ch per block; thread = 2 y-pixels x 32 co.
// 2 input channels per barrier stage; FFMA2 packed accumulation.
// ---------------------------------------------------------------------------
__global__ __launch_bounds__(256) void conv3x3_kernel(
    const float* __restrict__ x, const float* __restrict__ w1,
    const float* __restrict__ b1)
{
    const int tx = threadIdx.x;            // 0..31
    const int ty = threadIdx.y;            // 0..7
    const int tid = ty * 32 + tx;
    const int tileX = blockIdx.x * 32;
    const int tileY = blockIdx.y * 16;
    const int b = blockIdx.z >> 1;
    const int coBase = (blockIdx.z & 1) * 32;

    __shared__ __align__(16) float s_in[2][18][36];
    __shared__ __align__(16) float s_w[2][9][32];   // [ci2][tap][co]

    unsigned long long acc0[16], acc1[16];          // 32 co each, packed pairs
#pragma unroll
    for (int i = 0; i < 16; ++i) { acc0[i] = 0ull; acc1[i] = 0ull; }

    for (int ci0 = 0; ci0 < CIN; ci0 += 2) {
#pragma unroll
        for (int cc = 0; cc < 2; ++cc) {
            const float* xp = x + ((size_t)(b * CIN + ci0 + cc)) * HWi;
            for (int e = tid; e < 18 * 34; e += 256) {
                int r = e / 34, c = e - r * 34;
                s_in[cc][r][c] = xp[(tileY + r) * Wn + (tileX + c)];
            }
        }
        // 2 ci x 9 taps x 32 co = 576 weights
        for (int e = tid; e < 576; e += 256) {
            int co = e & 31;
            int k  = (e >> 5) % 9;
            int cc = e / 288;
            s_w[cc][k][co] = w1[((size_t)(coBase + co) * CIN + ci0 + cc) * 9 + k];
        }
        __syncthreads();

#pragma unroll
        for (int cc = 0; cc < 2; ++cc) {
            float in[4][3];
#pragma unroll
            for (int r = 0; r < 4; ++r)
#pragma unroll
                for (int c = 0; c < 3; ++c)
                    in[r][c] = s_in[cc][ty * 2 + r][tx + c];

#pragma unroll
            for (int ky = 0; ky < 3; ++ky)
#pragma unroll
                for (int kx = 0; kx < 3; ++kx) {
                    unsigned long long i0 = pack2(in[ky][kx]);
                    unsigned long long i1 = pack2(in[ky + 1][kx]);
                    const ulonglong2* wp = (const ulonglong2*)s_w[cc][ky * 3 + kx];
#pragma unroll
                    for (int q = 0; q < 8; ++q) {
                        ulonglong2 w = wp[q];
                        ffma2(acc0[q * 2 + 0], w.x, i0);
                        ffma2(acc0[q * 2 + 1], w.y, i0);
                        ffma2(acc1[q * 2 + 0], w.x, i1);
                        ffma2(acc1[q * 2 + 1], w.y, i1);
                    }
                }
        }
        __syncthreads();
    }

    const int oy = tileY + ty * 2;
    const int ox = tileX + tx;
#pragma unroll
    for (int q = 0; q < 16; ++q) {
        float a0lo, a0hi, a1lo, a1hi;
        unpack2(acc0[q], a0lo, a0hi);
        unpack2(acc1[q], a1lo, a1hi);
        int co = coBase + q * 2;
        float bb0 = b1[co], bb1 = b1[co + 1];
        size_t base0 = ((size_t)(b * COUT + co)) * HWo;
        size_t base1 = base0 + HWo;
        g_t[base0 + (size_t)oy * WOn + ox]       = a0lo + bb0;
        g_t[base0 + (size_t)(oy + 1) * WOn + ox] = a1lo + bb0;
        g_t[base1 + (size_t)oy * WOn + ox]       = a0hi + bb1;
        g_t[base1 + (size_t)(oy + 1) * WOn + ox] = a1hi + bb1;
    }
}

// ---------------------------------------------------------------------------
// Kernel 2: 1x1 conv 64->144 (offset prediction), FFMA2 packed.
// Block: 256 pixels x 48 out-ch, thread = 1 pixel, 24 packed acc.
// ---------------------------------------------------------------------------
__global__ __launch_bounds__(256, 2) void conv1x1_kernel(
    const float* __restrict__ w2, const float* __restrict__ b2,
    float* __restrict__ off)
{
    __shared__ __align__(16) float s_w[64 * 48];   // [cin][co48]
    __shared__ float s_t[16][256];

    const int tid = threadIdx.x;
    const int coBase = blockIdx.y * 48;
    const int p0 = blockIdx.x * 256;
    const int b = p0 >> 14;
    const int hwBase = p0 & (HWo - 1);

    for (int e = tid; e < 64 * 48; e += 256) {
        int cin = e / 48, co = e - cin * 48;
        s_w[e] = w2[(size_t)(coBase + co) * CIN + cin];
    }

    unsigned long long acc[24];
#pragma unroll
    for (int i = 0; i < 24; ++i) acc[i] = 0ull;

    for (int chunk = 0; chunk < 4; ++chunk) {
        __syncthreads();
#pragma unroll
        for (int r = 0; r < 16; ++r)
            s_t[r][tid] = g_t[((size_t)(b * CIN + chunk * 16 + r)) * HWo + hwBase + tid];
        __syncthreads();
#pragma unroll
        for (int r = 0; r < 16; ++r) {
            unsigned long long tv = pack2(s_t[r][tid]);
            const ulonglong2* wp = (const ulonglong2*)(s_w + (chunk * 16 + r) * 48);
#pragma unroll
            for (int q = 0; q < 12; ++q) {
                ulonglong2 w = wp[q];
                ffma2(acc[q * 2 + 0], w.x, tv);
                ffma2(acc[q * 2 + 1], w.y, tv);
            }
        }
    }

    const int hw = hwBase + tid;
#pragma unroll
    for (int q = 0; q < 24; ++q) {
        float lo, hi;
        unpack2(acc[q], lo, hi);
        int co = coBase + q * 2;
        off[((size_t)(b * OFFC + co)) * HWo + hw]     = lo + b2[co];
        off[((size_t)(b * OFFC + co + 1)) * HWo + hw] = hi + b2[co + 1];
    }
}

// ---------------------------------------------------------------------------
// Kernel 3: deformable conv, FFMA2 packed inner loop.
// Thread = 1 output pixel, 64 out channels (32 packed acc).
// Smem weights per group, layout [ij][c][co64] (co contiguous for pairs).
// ---------------------------------------------------------------------------
__global__ __launch_bounds__(256, 2) void deform_kernel(
    const float* __restrict__ x, const float* __restrict__ wd,
    const float* __restrict__ off, float* __restrict__ y)
{
    __shared__ __align__(16) float s_wd[9 * 8 * 64];   // [ij][c][co]

    const int tx = threadIdx.x;      // 0..31
    const int ty = threadIdx.y;      // 0..7
    const int tid = ty * 32 + tx;
    const int wo = blockIdx.x * 32 + tx;
    const int ho = blockIdx.y * 8 + ty;
    const int b = blockIdx.z;

    unsigned long long acc[32];
#pragma unroll
    for (int i = 0; i < 32; ++i) acc[i] = 0ull;

    for (int g = 0; g < Gn; ++g) {
        __syncthreads();   // previous group's compute done before overwrite
        for (int e = tid; e < 4608; e += 256) {
            int co = e & 63;
            int c  = (e >> 6) & 7;
            int ij = e >> 9;
            int i = ij / 3, j = ij - i * 3;
            s_wd[e] = wd[(((size_t)co * CIN + g * CPGn + c) * 3 + i) * 3 + j];
        }
        __syncthreads();

        const float* xg = x + ((size_t)(b * CIN + g * CPGn)) * HWi;

        for (int ij = 0; ij < 9; ++ij) {
            const int i = ij / 3, j = ij - i * 3;
            const int ch = (g * 9 + ij) * 2;
            const size_t obase = ((size_t)(b * OFFC + ch)) * HWo + ho * WOn + wo;
            float dy = __ldg(off + obase);
            float dx = __ldg(off + obase + HWo);

            float py = dy + (float)(ho + i);
            float px = dx + (float)(wo + j);
            float y0f = floorf(py), x0f = floorf(px);
            float ly = py - y0f, lx = px - x0f;
            int y0 = (int)y0f, x0 = (int)x0f;
            int y1 = y0 + 1, x1 = x0 + 1;

            float vy0 = (y0 >= 0 && y0 < Hn) ? 1.f : 0.f;
            float vy1 = (y1 >= 0 && y1 < Hn) ? 1.f : 0.f;
            float vx0 = (x0 >= 0 && x0 < Wn) ? 1.f : 0.f;
            float vx1 = (x1 >= 0 && x1 < Wn) ? 1.f : 0.f;

            float w00 = (1.f - ly) * (1.f - lx) * vy0 * vx0;
            float w01 = (1.f - ly) * lx * vy0 * vx1;
            float w10 = ly * (1.f - lx) * vy1 * vx0;
            float w11 = ly * lx * vy1 * vx1;

            int yc0 = min(max(y0, 0), Hn - 1), yc1 = min(max(y1, 0), Hn - 1);
            int xc0 = min(max(x0, 0), Wn - 1), xc1 = min(max(x1, 0), Wn - 1);
            int i00 = yc0 * Wn + xc0, i01 = yc0 * Wn + xc1;
            int i10 = yc1 * Wn + xc0, i11 = yc1 * Wn + xc1;

            unsigned long long vp[8];
#pragma unroll
            for (int c = 0; c < 8; ++c) {
                const float* p = xg + (size_t)c * HWi;
                float v = w00 * __ldg(p + i00) + w01 * __ldg(p + i01)
                        + w10 * __ldg(p + i10) + w11 * __ldg(p + i11);
                vp[c] = pack2(v);
            }

#pragma unroll
            for (int c = 0; c < 8; ++c) {
                const ulonglong2* wrow = (const ulonglong2*)(s_wd + (ij * 8 + c) * 64);
#pragma unroll
                for (int q = 0; q < 16; ++q) {
                    ulonglong2 w = wrow[q];
                    ffma2(acc[q * 2 + 0], w.x, vp[c]);
                    ffma2(acc[q * 2 + 1], w.y, vp[c]);
                }
            }
        }
    }

#pragma unroll
    for (int q = 0; q < 32; ++q) {
        float lo, hi;
        unpack2(acc[q], lo, hi);
        size_t base = ((size_t)(b * COUT + q * 2)) * HWo + ho * WOn + wo;
        y[base]       = lo;
        y[base + HWo] = hi;
    }
}

// ---------------------------------------------------------------------------
extern "C" void kernel_launch(void* const* d_in, const int* in_sizes, int n_in,
                              void* d_out, int out_size)
{
    const float* x  = (const float*)d_in[0];
    const float* w1 = (const float*)d_in[1];
    const float* b1 = (const float*)d_in[2];
    const float* w2 = (const float*)d_in[3];
    const float* b2 = (const float*)d_in[4];
    const float* wd = (const float*)d_in[5];

    float* y   = (float*)d_out;
    float* off = y + (size_t)Bn * COUT * HOn * WOn;   // off is output #2

    conv3x3_kernel<<<dim3(4, 8, Bn * 2), dim3(32, 8)>>>(x, w1, b1);
    conv1x1_kernel<<<dim3((Bn * HWo) / 256, 3), 256>>>(w2, b2, off);
    deform_kernel<<<dim3(WOn / 32, HOn / 8, Bn), dim3(32, 8)>>>(x, wd, off, y);
}

// round 8
// speedup vs baseline: 1.0626x; 1.0626x over previous
#include <cuda_runtime.h>

#define Bn   16
#define CIN  64
#define COUT 64
#define Hn   130
#define Wn   130
#define HOn  128
#define WOn  128
#define Gn   8
#define CPGn 8
#define OFFC 144   // G*2*K*K
#define HWo  16384 // 128*128
#define HWi  16900 // 130*130

// Intermediate feature map t = conv3x3(x, w1) + b1  : [16,64,128,128]
__device__ float g_t[(size_t)Bn * CIN * HOn * WOn];

// ---- packed fp32x2 helpers (Blackwell FFMA2, PTX-only) ---------------------
__device__ __forceinline__ unsigned long long pack2(float v) {
    unsigned long long r;
    asm("mov.b64 %0, {%1, %1};" : "=l"(r) : "f"(v));
    return r;
}
__device__ __forceinline__ void ffma2(unsigned long long& a,
                                      unsigned long long w,
                                      unsigned long long v) {
    asm("fma.rn.f32x2 %0, %1, %2, %0;" : "+l"(a) : "l"(w), "l"(v));
}
__device__ __forceinline__ void unpack2(unsigned long long a, float& lo, float& hi) {
    asm("mov.b64 {%0, %1}, %2;" : "=f"(lo), "=f"(hi) : "l"(a));
}

// ---------------------------------------------------------------------------
// Kernel 1: 3x3 VALID conv, 64->64.  SCALAR FFMA (reg-lean, occupancy first).
// Tile 32x16 spatial x 16 out-ch per block; thread = 2 y-pixels x 16 co.
// 2 input channels staged per barrier (half the syncs of round 3).
// ---------------------------------------------------------------------------
__global__ __launch_bounds__(256, 4) void conv3x3_kernel(
    const float* __restrict__ x, const float* __restrict__ w1,
    const float* __restrict__ b1)
{
    const int tx = threadIdx.x;            // 0..31
    const int ty = threadIdx.y;            // 0..7
    const int tid = ty * 32 + tx;
    const int tileX = blockIdx.x * 32;
    const int tileY = blockIdx.y * 16;
    const int b = blockIdx.z >> 2;
    const int coBase = (blockIdx.z & 3) * 16;

    __shared__ float s_in[2][18][36];   // 2 ci x (16+2) x (32+2), padded
    __shared__ float s_w[2][9][16];     // [ci2][tap][co]

    float acc0[16], acc1[16];
#pragma unroll
    for (int i = 0; i < 16; ++i) { acc0[i] = 0.f; acc1[i] = 0.f; }

    for (int ci0 = 0; ci0 < CIN; ci0 += 2) {
#pragma unroll
        for (int cc = 0; cc < 2; ++cc) {
            const float* xp = x + ((size_t)(b * CIN + ci0 + cc)) * HWi;
            for (int e = tid; e < 18 * 34; e += 256) {
                int r = e / 34, c = e - r * 34;
                s_in[cc][r][c] = xp[(tileY + r) * Wn + (tileX + c)];
            }
        }
        for (int e = tid; e < 288; e += 256) {
            int cc = e / 144;
            int k  = (e % 144) >> 4;
            int co = e & 15;
            s_w[cc][k][co] = w1[((size_t)(coBase + co) * CIN + ci0 + cc) * 9 + k];
        }
        __syncthreads();

#pragma unroll
        for (int cc = 0; cc < 2; ++cc) {
            float in[4][3];
#pragma unroll
            for (int r = 0; r < 4; ++r)
#pragma unroll
                for (int c = 0; c < 3; ++c)
                    in[r][c] = s_in[cc][ty * 2 + r][tx + c];

#pragma unroll
            for (int ky = 0; ky < 3; ++ky)
#pragma unroll
                for (int kx = 0; kx < 3; ++kx) {
                    float i0 = in[ky][kx];
                    float i1 = in[ky + 1][kx];
                    const float4* w4 = (const float4*)s_w[cc][ky * 3 + kx];
#pragma unroll
                    for (int q = 0; q < 4; ++q) {
                        float4 w = w4[q];
                        acc0[q * 4 + 0] += i0 * w.x;
                        acc0[q * 4 + 1] += i0 * w.y;
                        acc0[q * 4 + 2] += i0 * w.z;
                        acc0[q * 4 + 3] += i0 * w.w;
                        acc1[q * 4 + 0] += i1 * w.x;
                        acc1[q * 4 + 1] += i1 * w.y;
                        acc1[q * 4 + 2] += i1 * w.z;
                        acc1[q * 4 + 3] += i1 * w.w;
                    }
                }
        }
        __syncthreads();
    }

    const int oy = tileY + ty * 2;
    const int ox = tileX + tx;
#pragma unroll
    for (int co = 0; co < 16; ++co) {
        float bb = b1[coBase + co];
        size_t base = ((size_t)(b * COUT + coBase + co)) * HWo;
        g_t[base + (size_t)oy * WOn + ox]       = acc0[co] + bb;
        g_t[base + (size_t)(oy + 1) * WOn + ox] = acc1[co] + bb;
    }
}

// ---------------------------------------------------------------------------
// Kernel 2: 1x1 conv 64->144 (offset prediction), FFMA2 packed (reg-neutral).
// Block: 256 pixels x 48 out-ch, thread = 1 pixel, 24 packed acc.
// ---------------------------------------------------------------------------
__global__ __launch_bounds__(256, 2) void conv1x1_kernel(
    const float* __restrict__ w2, const float* __restrict__ b2,
    float* __restrict__ off)
{
    __shared__ __align__(16) float s_w[64 * 48];   // [cin][co48]
    __shared__ float s_t[16][256];

    const int tid = threadIdx.x;
    const int coBase = blockIdx.y * 48;
    const int p0 = blockIdx.x * 256;
    const int b = p0 >> 14;
    const int hwBase = p0 & (HWo - 1);

    for (int e = tid; e < 64 * 48; e += 256) {
        int cin = e / 48, co = e - cin * 48;
        s_w[e] = w2[(size_t)(coBase + co) * CIN + cin];
    }

    unsigned long long acc[24];
#pragma unroll
    for (int i = 0; i < 24; ++i) acc[i] = 0ull;

    for (int chunk = 0; chunk < 4; ++chunk) {
        __syncthreads();
#pragma unroll
        for (int r = 0; r < 16; ++r)
            s_t[r][tid] = g_t[((size_t)(b * CIN + chunk * 16 + r)) * HWo + hwBase + tid];
        __syncthreads();
#pragma unroll
        for (int r = 0; r < 16; ++r) {
            unsigned long long tv = pack2(s_t[r][tid]);
            const ulonglong2* wp = (const ulonglong2*)(s_w + (chunk * 16 + r) * 48);
#pragma unroll
            for (int q = 0; q < 12; ++q) {
                ulonglong2 w = wp[q];
                ffma2(acc[q * 2 + 0], w.x, tv);
                ffma2(acc[q * 2 + 1], w.y, tv);
            }
        }
    }

    const int hw = hwBase + tid;
#pragma unroll
    for (int q = 0; q < 24; ++q) {
        float lo, hi;
        unpack2(acc[q], lo, hi);
        int co = coBase + q * 2;
        off[((size_t)(b * OFFC + co)) * HWo + hw]     = lo + b2[co];
        off[((size_t)(b * OFFC + co + 1)) * HWo + hw] = hi + b2[co + 1];
    }
}

// ---------------------------------------------------------------------------
// Kernel 3: deformable conv. FFMA2 accumulate (reg-neutral: 32 u64 = 64 regs).
// Offsets for all 9 taps of a group hoisted ahead of the tap loop (removes the
// per-tap serial offset-LDG latency chain). Gather + accumulate interleaved
// per input channel to keep live ranges small.
// ---------------------------------------------------------------------------
__global__ __launch_bounds__(256, 2) void deform_kernel(
    const float* __restrict__ x, const float* __restrict__ wd,
    const float* __restrict__ off, float* __restrict__ y)
{
    __shared__ __align__(16) float s_wd[9 * 8 * 64];   // [ij][c][co]

    const int tx = threadIdx.x;      // 0..31
    const int ty = threadIdx.y;      // 0..7
    const int tid = ty * 32 + tx;
    const int wo = blockIdx.x * 32 + tx;
    const int ho = blockIdx.y * 8 + ty;
    const int b = blockIdx.z;

    unsigned long long acc[32];
#pragma unroll
    for (int i = 0; i < 32; ++i) acc[i] = 0ull;

    for (int g = 0; g < Gn; ++g) {
        __syncthreads();   // previous group's compute done before overwrite
        for (int e = tid; e < 4608; e += 256) {
            int co = e & 63;
            int c  = (e >> 6) & 7;
            int ij = e >> 9;
            int i = ij / 3, j = ij - i * 3;
            s_wd[e] = wd[(((size_t)co * CIN + g * CPGn + c) * 3 + i) * 3 + j];
        }
        __syncthreads();

        // Hoist all 18 offset loads for this group (full MLP, one latency).
        float dyv[9], dxv[9];
#pragma unroll
        for (int ij = 0; ij < 9; ++ij) {
            const size_t obase = ((size_t)(b * OFFC + (g * 9 + ij) * 2)) * HWo
                               + ho * WOn + wo;
            dyv[ij] = __ldg(off + obase);
            dxv[ij] = __ldg(off + obase + HWo);
        }

        const float* xg = x + ((size_t)(b * CIN + g * CPGn)) * HWi;

        for (int ij = 0; ij < 9; ++ij) {
            const int i = ij / 3, j = ij - i * 3;

            float py = dyv[ij] + (float)(ho + i);
            float px = dxv[ij] + (float)(wo + j);
            float y0f = floorf(py), x0f = floorf(px);
            float ly = py - y0f, lx = px - x0f;
            int y0 = (int)y0f, x0 = (int)x0f;
            int y1 = y0 + 1, x1 = x0 + 1;

            float vy0 = (y0 >= 0 && y0 < Hn) ? 1.f : 0.f;
            float vy1 = (y1 >= 0 && y1 < Hn) ? 1.f : 0.f;
            float vx0 = (x0 >= 0 && x0 < Wn) ? 1.f : 0.f;
            float vx1 = (x1 >= 0 && x1 < Wn) ? 1.f : 0.f;

            float w00 = (1.f - ly) * (1.f - lx) * vy0 * vx0;
            float w01 = (1.f - ly) * lx * vy0 * vx1;
            float w10 = ly * (1.f - lx) * vy1 * vx0;
            float w11 = ly * lx * vy1 * vx1;

            int yc0 = min(max(y0, 0), Hn - 1), yc1 = min(max(y1, 0), Hn - 1);
            int xc0 = min(max(x0, 0), Wn - 1), xc1 = min(max(x1, 0), Wn - 1);
            int i00 = yc0 * Wn + xc0, i01 = yc0 * Wn + xc1;
            int i10 = yc1 * Wn + xc0, i11 = yc1 * Wn + xc1;

#pragma unroll
            for (int c = 0; c < 8; ++c) {
                const float* p = xg + (size_t)c * HWi;
                float v = w00 * __ldg(p + i00) + w01 * __ldg(p + i01)
                        + w10 * __ldg(p + i10) + w11 * __ldg(p + i11);
                unsigned long long vp = pack2(v);
                const ulonglong2* wrow = (const ulonglong2*)(s_wd + (ij * 8 + c) * 64);
#pragma unroll
                for (int q = 0; q < 16; ++q) {
                    ulonglong2 w = wrow[q];
                    ffma2(acc[q * 2 + 0], w.x, vp);
                    ffma2(acc[q * 2 + 1], w.y, vp);
                }
            }
        }
    }

#pragma unroll
    for (int q = 0; q < 32; ++q) {
        float lo, hi;
        unpack2(acc[q], lo, hi);
        size_t base = ((size_t)(b * COUT + q * 2)) * HWo + ho * WOn + wo;
        y[base]       = lo;
        y[base + HWo] = hi;
    }
}

// ---------------------------------------------------------------------------
extern "C" void kernel_launch(void* const* d_in, const int* in_sizes, int n_in,
                              void* d_out, int out_size)
{
    const float* x  = (const float*)d_in[0];
    const float* w1 = (const float*)d_in[1];
    const float* b1 = (const float*)d_in[2];
    const float* w2 = (const float*)d_in[3];
    const float* b2 = (const float*)d_in[4];
    const float* wd = (const float*)d_in[5];

    float* y   = (float*)d_out;
    float* off = y + (size_t)Bn * COUT * HOn * WOn;   // off is output #2

    conv3x3_kernel<<<dim3(4, 8, Bn * 4), dim3(32, 8)>>>(x, w1, b1);
    conv1x1_kernel<<<dim3((Bn * HWo) / 256, 3), 256>>>(w2, b2, off);
    deform_kernel<<<dim3(WOn / 32, HOn / 8, Bn), dim3(32, 8)>>>(x, wd, off, y);
}